// round 2
// baseline (speedup 1.0000x reference)
#include <cuda_runtime.h>

#define TQ  64
#define TK  64
#define WIN 256
#define SEQ 4096

__device__ __forceinline__ unsigned long long ffma2(unsigned long long a, unsigned long long b, unsigned long long c) {
    unsigned long long d;
    asm("fma.rn.f32x2 %0, %1, %2, %3;" : "=l"(d) : "l"(a), "l"(b), "l"(c));
    return d;
}
__device__ __forceinline__ unsigned long long fmul2(unsigned long long a, unsigned long long b) {
    unsigned long long d;
    asm("mul.rn.f32x2 %0, %1, %2;" : "=l"(d) : "l"(a), "l"(b));
    return d;
}
__device__ __forceinline__ unsigned long long packf2(float lo, float hi) {
    unsigned long long d;
    asm("mov.b64 %0, {%1, %2};" : "=l"(d) : "f"(lo), "f"(hi));
    return d;
}
__device__ __forceinline__ void unpackf2(unsigned long long v, float &lo, float &hi) {
    asm("mov.b64 {%0, %1}, %2;" : "=f"(lo), "=f"(hi) : "l"(v));
}
__device__ __forceinline__ float ex2(float x) {
    float r;
    asm("ex2.approx.ftz.f32 %0, %1;" : "=f"(r) : "f"(x));
    return r;
}

// Each CTA: one batch b, 64 consecutive queries. 128 threads; thread pair
// (2*qi, 2*qi+1) owns query q0+qi, each half owning 32 of the 64 dims.
// K/V tiles staged in smem with dim-halves interleaved at float4 granularity
// (slot = c*2 + h) so the two halves' broadcast addresses are 16B apart.
__global__ __launch_bounds__(128) void swa_kernel(const float* __restrict__ qkv,
                                                  float* __restrict__ out)
{
    __shared__ float4 sKV[TK][32];   // per row: slots 0..15 = K (interleaved), 16..31 = V

    const int b  = blockIdx.y;
    const int q0 = blockIdx.x * TQ;
    const int t  = threadIdx.x;
    const int qi = t >> 1;
    const int h  = t & 1;
    const int iq = q0 + qi;

    // Load this thread's 32 Q dims, packed as 16 f32x2 registers.
    unsigned long long q2[16];
    {
        const float4* qg = reinterpret_cast<const float4*>(
            qkv + (size_t)(b * SEQ + iq) * 192 + h * 32);
        #pragma unroll
        for (int c = 0; c < 8; c++) {
            float4 v = qg[c];
            q2[c * 2 + 0] = packf2(v.x, v.y);
            q2[c * 2 + 1] = packf2(v.z, v.w);
        }
    }

    unsigned long long o2[16];
    #pragma unroll
    for (int i = 0; i < 16; i++) o2[i] = 0ull;
    float m = -1e30f, l = 0.0f;
    const float SCL = 0.125f * 1.44269504f;   // 1/sqrt(64) * log2(e)

    // Per-thread loader coordinates (constant across tiles).
    const int lrow  = t >> 2;                 // 0..31 (two rows per iteration pair)
    const int lc0   = (t & 3) * 8;            // base float4 column, 0/8/16/24

    // Iterate key tiles diagonal-first (reverse) so the very first 16-key chunk
    // always contains a valid key -> running max is finite before any
    // fully-masked chunk can appear.
    for (int k0 = q0; k0 >= 0 && k0 >= q0 - WIN; k0 -= TK) {
        __syncthreads();   // protect previous tile's consumers
        // Cooperative K/V tile load: 64 rows x 32 float4 (16 K + 16 V per row).
        // Each thread loads 8 contiguous float4 from each of 2 rows.
        #pragma unroll
        for (int half = 0; half < 2; half++) {
            int row = lrow + half * 32;
            const float4* rp = reinterpret_cast<const float4*>(
                qkv + (size_t)(b * SEQ + k0 + row) * 192) + 16;
            #pragma unroll
            for (int u = 0; u < 8; u++) {
                int c  = lc0 + u;                 // 0..31
                int cc = c & 15;
                int slot = (c < 16 ? 0 : 16) + ((cc & 7) * 2 + (cc >> 3));
                sKV[row][slot] = rp[c];           // floats 64..191 = K then V
            }
        }
        __syncthreads();

        #pragma unroll
        for (int ch = 0; ch < TK; ch += 16) {
            float sc[16];
            #pragma unroll
            for (int jj = 0; jj < 16; jj++) {
                int j = ch + jj;
                const unsigned long long* kr =
                    reinterpret_cast<const unsigned long long*>(&sKV[j][0]);
                unsigned long long acc = 0ull;   // (0.0f, 0.0f)
                #pragma unroll
                for (int c = 0; c < 8; c++) {
                    int u = (c * 2 + h) * 2;
                    acc = ffma2(q2[c * 2 + 0], kr[u + 0], acc);
                    acc = ffma2(q2[c * 2 + 1], kr[u + 1], acc);
                }
                float lo, hi;
                unpackf2(acc, lo, hi);
                float s = lo + hi;
                s += __shfl_xor_sync(0xffffffffu, s, 1);   // partner half
                int jg = k0 + j;
                bool valid = (jg <= iq) && (jg >= iq - WIN);
                sc[jj] = valid ? s * SCL : -1e30f;
            }
            // chunk max + online-softmax rescale
            float cm = sc[0];
            #pragma unroll
            for (int jj = 1; jj < 16; jj++) cm = fmaxf(cm, sc[jj]);
            float mn = fmaxf(m, cm);
            float corr = ex2(m - mn);
            m = mn;
            l *= corr;
            unsigned long long c2 = packf2(corr, corr);
            #pragma unroll
            for (int i = 0; i < 16; i++) o2[i] = fmul2(o2[i], c2);
            // accumulate P @ V
            #pragma unroll
            for (int jj = 0; jj < 16; jj++) {
                float p = ex2(sc[jj] - m);
                l += p;
                unsigned long long p2 = packf2(p, p);
                const unsigned long long* vr =
                    reinterpret_cast<const unsigned long long*>(&sKV[ch + jj][16]);
                #pragma unroll
                for (int c = 0; c < 8; c++) {
                    int u = (c * 2 + h) * 2;
                    o2[c * 2 + 0] = ffma2(p2, vr[u + 0], o2[c * 2 + 0]);
                    o2[c * 2 + 1] = ffma2(p2, vr[u + 1], o2[c * 2 + 1]);
                }
            }
        }
    }

    float rl = 1.0f / l;
    float* op = out + (size_t)(b * SEQ + iq) * 64 + h * 32;
    #pragma unroll
    for (int c = 0; c < 8; c++) {
        float lo0, hi0, lo1, hi1;
        unpackf2(o2[c * 2 + 0], lo0, hi0);
        unpackf2(o2[c * 2 + 1], lo1, hi1);
        reinterpret_cast<float4*>(op)[c] =
            make_float4(lo0 * rl, hi0 * rl, lo1 * rl, hi1 * rl);
    }
}

extern "C" void kernel_launch(void* const* d_in, const int* in_sizes, int n_in,
                              void* d_out, int out_size)
{
    const float* qkv = (const float*)d_in[0];
    float* out = (float*)d_out;
    int B = in_sizes[0] / (SEQ * 192);
    dim3 grid(SEQ / TQ, B);
    swa_kernel<<<grid, 128>>>(qkv, out);
}